// round 15
// baseline (speedup 1.0000x reference)
#include <cuda_runtime.h>
#include <cuda_bf16.h>
#include <math.h>
#include <stdint.h>

#define BB 4
#define CIN 64
#define HH 128
#define WW 128
#define HWSZ (HH*WW)
#define COUT 64
#define C27 27
#define CK 576  // CIN*9

// ---------------- device scratch (no allocs allowed) ----------------
// x in c8-blocked layout: [b][c/8][hw][c%8], pixel stride 32B
__device__ __align__(16) float g_x8[BB*8*HWSZ*8];
// main-conv B per tap: [k][oc 64][c 64] bf16 hi/lo
__device__ __align__(16) __nv_bfloat16 g_wBh[9*4096];
__device__ __align__(16) __nv_bfloat16 g_wBl[9*4096];
// offset-conv B per tap: [k][oc 32 (27 padded)][c 64] bf16 hi/lo
__device__ __align__(16) __nv_bfloat16 g_oBh[9*2048];
__device__ __align__(16) __nv_bfloat16 g_oBl[9*2048];

typedef unsigned long long u64;

// ---------------- helpers ----------------
__device__ __forceinline__ uint32_t smem_u32(const void* p) {
    uint32_t a;
    asm("{ .reg .u64 t; cvta.to.shared.u64 t, %1; cvt.u32.u64 %0, t; }" : "=r"(a) : "l"(p));
    return a;
}
__device__ __forceinline__ void cp_async16(uint32_t smem_dst, const void* gsrc) {
    asm volatile("cp.async.cg.shared.global [%0], [%1], 16;" :: "r"(smem_dst), "l"(gsrc));
}
__device__ __forceinline__ void sts128(uint32_t addr, uint32_t r0, uint32_t r1, uint32_t r2, uint32_t r3) {
    asm volatile("st.shared.v4.b32 [%0], {%1, %2, %3, %4};" :: "r"(addr), "r"(r0), "r"(r1), "r"(r2), "r"(r3) : "memory");
}
__device__ __forceinline__ void ldsm4(uint32_t a, uint32_t& r0, uint32_t& r1, uint32_t& r2, uint32_t& r3) {
    asm volatile("ldmatrix.sync.aligned.m8n8.x4.shared.b16 {%0,%1,%2,%3}, [%4];"
                 : "=r"(r0), "=r"(r1), "=r"(r2), "=r"(r3) : "r"(a));
}
__device__ __forceinline__ void mma16816(float* d, const uint32_t* a, const uint32_t* b) {
    asm volatile("mma.sync.aligned.m16n8k16.row.col.f32.bf16.bf16.f32 "
                 "{%0,%1,%2,%3}, {%4,%5,%6,%7}, {%8,%9}, {%0,%1,%2,%3};"
                 : "+f"(d[0]), "+f"(d[1]), "+f"(d[2]), "+f"(d[3])
                 : "r"(a[0]), "r"(a[1]), "r"(a[2]), "r"(a[3]), "r"(b[0]), "r"(b[1]));
}
// split f32 pair -> bf16x2 hi (truncate) + bf16x2 lo (residual, rounded)
__device__ __forceinline__ void split2(float v0, float v1, uint32_t& hi, uint32_t& lo) {
    uint32_t b0 = __float_as_uint(v0) & 0xFFFF0000u;
    uint32_t b1 = __float_as_uint(v1) & 0xFFFF0000u;
    hi = (b0 >> 16) | b1;
    float l0 = v0 - __uint_as_float(b0);
    float l1 = v1 - __uint_as_float(b1);
    asm("cvt.rn.bf16x2.f32 %0, %1, %2;" : "=r"(lo) : "f"(l1), "f"(l0));
}

#define PITCH 144

// ---------------------------------------------------------------------------
// Kernel -1: NCHW -> c8-blocked transpose. Coalesced reads per c-plane,
// per-thread 32B contiguous writes.
// ---------------------------------------------------------------------------
__global__ __launch_bounds__(256) void x8_kernel(const float* __restrict__ x) {
    int t  = blockIdx.x * 256 + threadIdx.x;   // BB*8*HWSZ = 524288
    int hw = t & (HWSZ - 1);
    int cb = (t >> 14) & 7;
    int b  = t >> 17;
    const float* src = x + ((size_t)(b*CIN + cb*8)) * HWSZ + hw;
    float4 v0, v1;
    v0.x = __ldg(src);
    v0.y = __ldg(src + HWSZ);
    v0.z = __ldg(src + 2*HWSZ);
    v0.w = __ldg(src + 3*HWSZ);
    v1.x = __ldg(src + 4*HWSZ);
    v1.y = __ldg(src + 5*HWSZ);
    v1.z = __ldg(src + 6*HWSZ);
    v1.w = __ldg(src + 7*HWSZ);
    float4* dst = (float4*)(g_x8 + (((size_t)(b*8 + cb)) * HWSZ + hw) * 8);
    dst[0] = v0;
    dst[1] = v1;
}

// ---------------------------------------------------------------------------
// Kernel 0: weight prep -> bf16 hi/lo B tiles for both convs
// ---------------------------------------------------------------------------
__global__ void prep_kernel(const float* __restrict__ wt, const float* __restrict__ owt) {
    int idx = blockIdx.x * blockDim.x + threadIdx.x;    // 144*256 = 36864
    if (idx < 9*4096) {
        int k  = idx >> 12;
        int oc = (idx >> 6) & 63;
        int c  = idx & 63;
        float w = wt[oc*CK + c*9 + k];
        uint32_t wb  = __float_as_uint(w);
        uint32_t hib = wb & 0xFFFF0000u;
        int d = k*4096 + oc*64 + c;
        ((uint16_t*)g_wBh)[d] = (uint16_t)(hib >> 16);
        g_wBl[d] = __float2bfloat16(w - __uint_as_float(hib));
    }
    if (idx < 9*2048) {
        int k  = idx >> 11;
        int oc = (idx >> 6) & 31;
        int c  = idx & 63;
        float w = (oc < C27) ? owt[oc*CK + c*9 + k] : 0.f;
        uint32_t wb  = __float_as_uint(w);
        uint32_t hib = wb & 0xFFFF0000u;
        int d = k*2048 + oc*64 + c;
        ((uint16_t*)g_oBh)[d] = (uint16_t)(hib >> 16);
        g_oBl[d] = __float2bfloat16(w - __uint_as_float(hib));
    }
}

// ---------------------------------------------------------------------------
// Fused kernel: offset/mask conv (phase 1) + deformable conv (phase 2).
// R15: all x reads via c8-blocked layout (LDG.128 per 4 channels).
// Warps 2x2 (m32 x n32 phase 2, m32 x n16 phase 1), strips, tap stagger.
// ---------------------------------------------------------------------------
#define FA_HI 0              // 66 rows * 144 = 9504
#define FA_LO 9504
#define FB_HI 19008
#define FB_LO 28224
#define FOM   37440          // om smem: [27][64] f32 = 6912 B
#define F_TOT 44352

__global__ __launch_bounds__(128, 4) void fused_dcn_kernel(const float* __restrict__ ob,
                                                           const float* __restrict__ bias,
                                                           float* __restrict__ out) {
    extern __shared__ __align__(16) char smem[];
    uint32_t sb = smem_u32(smem);
    int tid  = threadIdx.x;
    int lane = tid & 31, wid = tid >> 5;       // 4 warps, 2x2 tiling
    int mw   = wid & 1;                        // warp M row (m32)
    int nw   = wid >> 1;                       // warp N col
    int b    = blockIdx.x >> 8;                // 256 blocks per image
    int h    = (blockIdx.x >> 1) & 127;
    int px0  = (blockIdx.x & 1) * 64;          // which half-row
    int pxl  = tid & 63;                       // local px 0..63
    int px   = px0 + pxl;                      // w coordinate
    int c0   = (tid >> 6) * 32;                // 2 threads per px
    int kst  = (int)(blockIdx.x % 9u);         // tap stagger (phase 2)
    int kst3 = (int)(blockIdx.x % 3u);         // strip stagger (phase 1)

    const float* x8b = g_x8 + (size_t)b * (8 * HWSZ * 8);

    int seg = lane >> 3, r8 = lane & 7;
    uint32_t aBaseH = sb + FA_HI + (uint32_t)(((seg&1)*8 + r8) * PITCH + (seg>>1)*16);
    uint32_t aBaseL = aBaseH + (FA_LO - FA_HI);
    uint32_t aOff0  = (uint32_t)((mw*32)      * PITCH);
    uint32_t aOff1  = (uint32_t)((mw*32 + 16) * PITCH);
    uint32_t bColB  = (uint32_t)((seg&1)*16);
    uint32_t bRowB  = (uint32_t)(((seg>>1)*8 + r8) * PITCH);

    // =====================================================================
    // Phase 1: offset/mask conv (N=32), strip-based A, result -> smem om
    // =====================================================================
    {
        float acco[4][4] = {};   // [mt*2 + nc][4]

        #pragma unroll 1
        for (int js = 0; js < 3; js++) {
            int kh = kst3 + js; if (kh >= 3) kh -= 3;

            // ---- build strip: image row h-1+kh, cols px0-1..px0+64, 64 c ----
            #pragma unroll
            for (int it = 0; it < 2; it++) {
                int idx = tid + it*128;
                if (idx < 132) {
                    int r   = idx % 66;
                    int ch2 = idx / 66;
                    int cb0 = ch2 * 4;               // first c8 block
                    int row = h - 1 + kh;
                    int col = px0 - 1 + r;
                    bool valid = (row >= 0) && (row < HH) && (col >= 0) && (col < WW);
                    size_t hwo = (size_t)(row*WW + col) * 8;
                    #pragma unroll
                    for (int g = 0; g < 4; g++) {
                        int cb = cb0 + g;
                        float4 u0 = {0,0,0,0}, u1 = {0,0,0,0};
                        if (valid) {
                            const float4* p = (const float4*)(x8b + (size_t)cb * (HWSZ*8) + hwo);
                            u0 = __ldg(p);
                            u1 = __ldg(p + 1);
                        }
                        uint32_t hi[4], lo[4];
                        split2(u0.x, u0.y, hi[0], lo[0]);
                        split2(u0.z, u0.w, hi[1], lo[1]);
                        split2(u1.x, u1.y, hi[2], lo[2]);
                        split2(u1.z, u1.w, hi[3], lo[3]);
                        uint32_t off = (uint32_t)(r*PITCH + cb*16);
                        sts128(sb + FA_HI + off, hi[0], hi[1], hi[2], hi[3]);
                        sts128(sb + FA_LO + off, lo[0], lo[1], lo[2], lo[3]);
                    }
                }
            }

            // ---- 3 kw taps over this strip ----
            #pragma unroll 1
            for (int kw = 0; kw < 3; kw++) {
                int k = kh*3 + kw;

                // stage offset B tiles (hi 4KB + lo 4KB = 512 x 16B chunks)
                #pragma unroll
                for (int i = 0; i < 4; i++) {
                    int e   = tid + i*128;
                    int t8  = e >> 8;
                    int cnk = e & 255;
                    int row = cnk >> 3, c16 = (cnk & 7) * 16;
                    const char* src = (t8 ? (const char*)g_oBl : (const char*)g_oBh)
                                      + (size_t)k*4096 + row*128 + c16;
                    uint32_t dst = sb + (t8 ? FB_LO : FB_HI) + (uint32_t)(row*PITCH + c16);
                    cp_async16(dst, src);
                }
                asm volatile("cp.async.commit_group;");
                asm volatile("cp.async.wait_group 0;");
                __syncthreads();   // B(k) + (first kw: strip) visible

                // MMA: A base shifted by kw rows within the strip
                uint32_t aShift = (uint32_t)(kw * PITCH);
                #pragma unroll
                for (int ks = 0; ks < 4; ks++) {
                    uint32_t ah[2][4], al[2][4];
                    ldsm4(aBaseH + aOff0 + aShift + ks*32, ah[0][0], ah[0][1], ah[0][2], ah[0][3]);
                    ldsm4(aBaseL + aOff0 + aShift + ks*32, al[0][0], al[0][1], al[0][2], al[0][3]);
                    ldsm4(aBaseH + aOff1 + aShift + ks*32, ah[1][0], ah[1][1], ah[1][2], ah[1][3]);
                    ldsm4(aBaseL + aOff1 + aShift + ks*32, al[1][0], al[1][1], al[1][2], al[1][3]);
                    uint32_t bh[2][2], bl[2][2];
                    {
                        uint32_t ra = bRowB + (uint32_t)(nw*16*PITCH) + bColB + ks*32;
                        ldsm4(sb + FB_HI + ra, bh[0][0], bh[0][1], bh[1][0], bh[1][1]);
                        ldsm4(sb + FB_LO + ra, bl[0][0], bl[0][1], bl[1][0], bl[1][1]);
                    }
                    #pragma unroll
                    for (int mt = 0; mt < 2; mt++)
                        #pragma unroll
                        for (int nc = 0; nc < 2; nc++) {
                            mma16816(acco[mt*2+nc], ah[mt], bh[nc]);
                            mma16816(acco[mt*2+nc], ah[mt], bl[nc]);
                            mma16816(acco[mt*2+nc], al[mt], bh[nc]);
                        }
                }
                __syncthreads();   // B / strip safe to overwrite
            }
        }

        // epilogue -> smem om buffer [27][64] f32 (bias + sigmoid on mask rows)
        {
            int nf = (lane & 3) * 2;
            #pragma unroll
            for (int mt = 0; mt < 2; mt++) {
                int ml = mw*32 + mt*16 + (lane >> 2);
                #pragma unroll
                for (int nc = 0; nc < 2; nc++) {
                    #pragma unroll
                    for (int half = 0; half < 2; half++) {
                        int nn = nw*16 + nc*8 + nf + half;
                        if (nn < C27) {
                            float bo = __ldg(ob + nn);
                            float v0 = acco[mt*2+nc][half]     + bo;   // row ml
                            float v1 = acco[mt*2+nc][half + 2] + bo;   // row ml+8
                            if (nn >= 18) {
                                v0 = 1.f / (1.f + __expf(-v0));
                                v1 = 1.f / (1.f + __expf(-v1));
                            }
                            uint32_t oa = sb + FOM + (uint32_t)((nn*64 + ml) * 4);
                            asm volatile("st.shared.f32 [%0], %1;" :: "r"(oa), "f"(v0) : "memory");
                            asm volatile("st.shared.f32 [%0], %1;" :: "r"(oa + 32), "f"(v1) : "memory");
                        }
                    }
                }
            }
        }
        __syncthreads();
    }

    // =====================================================================
    // Phase 2: deformable conv (N=64), om read from smem
    // =====================================================================
    float acc[8][4] = {};   // [mt*4 + nc][4]

    #pragma unroll 1
    for (int j = 0; j < 9; j++) {
        int k = kst + j; if (k >= 9) k -= 9;

        // stage main B tiles (hi+lo, 1024 x 16B chunks)
        #pragma unroll
        for (int i = 0; i < 8; i++) {
            int e   = tid + i*128;
            int t8  = e >> 9;
            int cnk = e & 511;
            int row = cnk >> 3, c16 = (cnk & 7) * 16;
            const char* src = (t8 ? (const char*)g_wBl : (const char*)g_wBh)
                              + (size_t)k*8192 + row*128 + c16;
            uint32_t dst = sb + (t8 ? FB_LO : FB_HI) + (uint32_t)(row*PITCH + c16);
            cp_async16(dst, src);
        }
        asm volatile("cp.async.commit_group;");

        // om from smem
        float dy, dx, m;
        {
            uint32_t oa = sb + FOM + (uint32_t)(pxl * 4);
            asm volatile("ld.shared.f32 %0, [%1];" : "=f"(dy) : "r"(oa + (uint32_t)(k*256)));
            asm volatile("ld.shared.f32 %0, [%1];" : "=f"(dx) : "r"(oa + (uint32_t)((9+k)*256)));
            asm volatile("ld.shared.f32 %0, [%1];" : "=f"(m)  : "r"(oa + (uint32_t)((18+k)*256)));
        }

        // bilinear params
        int kh = k / 3, kw = k - kh*3;
        float hh = (float)(h - 1 + kh) + dy;
        float ww = (float)(px - 1 + kw) + dx;
        float h0f = floorf(hh), w0f = floorf(ww);
        float lh = hh - h0f, lw = ww - w0f;
        int h0 = (int)h0f, w0 = (int)w0f, h1 = h0+1, w1 = w0+1;
        bool vh0 = (h0>=0)&&(h0<HH), vh1 = (h1>=0)&&(h1<HH);
        bool vw0 = (w0>=0)&&(w0<WW), vw1 = (w1>=0)&&(w1<WW);
        int ch0 = min(max(h0,0),HH-1), ch1 = min(max(h1,0),HH-1);
        int cw0 = min(max(w0,0),WW-1), cw1 = min(max(w1,0),WW-1);
        size_t o00 = (size_t)(ch0*WW+cw0) * 8, o01 = (size_t)(ch0*WW+cw1) * 8;
        size_t o10 = (size_t)(ch1*WW+cw0) * 8, o11 = (size_t)(ch1*WW+cw1) * 8;
        float w00 = (1.f-lh)*(1.f-lw)*m*((vh0&&vw0)?1.f:0.f);
        float w01 = (1.f-lh)*lw      *m*((vh0&&vw1)?1.f:0.f);
        float w10 = lh*(1.f-lw)      *m*((vh1&&vw0)?1.f:0.f);
        float w11 = lh*lw            *m*((vh1&&vw1)?1.f:0.f);

        // produce A tile: c8-blocked vector gathers (8x LDG.128 per 8 ch)
        #pragma unroll 1
        for (int g = 0; g < 4; g++) {
            int cb = (c0 >> 3) + g;
            const float* xc = x8b + (size_t)cb * (HWSZ*8);
            float4 a0 = __ldg((const float4*)(xc + o00));
            float4 a1 = __ldg((const float4*)(xc + o00) + 1);
            float4 b0 = __ldg((const float4*)(xc + o01));
            float4 b1 = __ldg((const float4*)(xc + o01) + 1);
            float4 c0v = __ldg((const float4*)(xc + o10));
            float4 c1v = __ldg((const float4*)(xc + o10) + 1);
            float4 d0 = __ldg((const float4*)(xc + o11));
            float4 d1 = __ldg((const float4*)(xc + o11) + 1);
            float v[8];
            v[0] = fmaf(w11, d0.x, fmaf(w10, c0v.x, fmaf(w01, b0.x, w00*a0.x)));
            v[1] = fmaf(w11, d0.y, fmaf(w10, c0v.y, fmaf(w01, b0.y, w00*a0.y)));
            v[2] = fmaf(w11, d0.z, fmaf(w10, c0v.z, fmaf(w01, b0.z, w00*a0.z)));
            v[3] = fmaf(w11, d0.w, fmaf(w10, c0v.w, fmaf(w01, b0.w, w00*a0.w)));
            v[4] = fmaf(w11, d1.x, fmaf(w10, c1v.x, fmaf(w01, b1.x, w00*a1.x)));
            v[5] = fmaf(w11, d1.y, fmaf(w10, c1v.y, fmaf(w01, b1.y, w00*a1.y)));
            v[6] = fmaf(w11, d1.z, fmaf(w10, c1v.z, fmaf(w01, b1.z, w00*a1.z)));
            v[7] = fmaf(w11, d1.w, fmaf(w10, c1v.w, fmaf(w01, b1.w, w00*a1.w)));
            uint32_t hi[4], lo[4];
            #pragma unroll
            for (int j4 = 0; j4 < 4; j4++) split2(v[2*j4], v[2*j4+1], hi[j4], lo[j4]);
            uint32_t off = (uint32_t)(pxl*PITCH + cb*16);
            sts128(sb + FA_HI + off, hi[0], hi[1], hi[2], hi[3]);
            sts128(sb + FA_LO + off, lo[0], lo[1], lo[2], lo[3]);
        }

        asm volatile("cp.async.wait_group 0;");
        __syncthreads();

        // MMA: 4 ks x (4 A-ldsm + 4 B-ldsm + 24 mma), warp tile m32 x n32
        #pragma unroll
        for (int ks = 0; ks < 4; ks++) {
            uint32_t ah[2][4], al[2][4];
            ldsm4(aBaseH + aOff0 + ks*32, ah[0][0], ah[0][1], ah[0][2], ah[0][3]);
            ldsm4(aBaseL + aOff0 + ks*32, al[0][0], al[0][1], al[0][2], al[0][3]);
            ldsm4(aBaseH + aOff1 + ks*32, ah[1][0], ah[1][1], ah[1][2], ah[1][3]);
            ldsm4(aBaseL + aOff1 + ks*32, al[1][0], al[1][1], al[1][2], al[1][3]);
            uint32_t bh[4][2], bl[4][2];
            #pragma unroll
            for (int q = 0; q < 2; q++) {
                uint32_t ra = bRowB + (uint32_t)((nw*32 + q*16)*PITCH) + bColB + ks*32;
                ldsm4(sb + FB_HI + ra, bh[2*q][0], bh[2*q][1], bh[2*q+1][0], bh[2*q+1][1]);
                ldsm4(sb + FB_LO + ra, bl[2*q][0], bl[2*q][1], bl[2*q+1][0], bl[2*q+1][1]);
            }
            #pragma unroll
            for (int mt = 0; mt < 2; mt++)
                #pragma unroll
                for (int nc = 0; nc < 4; nc++) {
                    mma16816(acc[mt*4+nc], ah[mt], bh[nc]);
                    mma16816(acc[mt*4+nc], ah[mt], bl[nc]);
                    mma16816(acc[mt*4+nc], al[mt], bh[nc]);
                }
        }
        __syncthreads();
    }

    // ---- epilogue ----
    {
        int nf = (lane & 3) * 2;
        #pragma unroll
        for (int mt = 0; mt < 2; mt++) {
            int ml = mw*32 + mt*16 + (lane >> 2);
            float* obp = out + (size_t)b * COUT * HWSZ + (h << 7) + px0 + ml;
            #pragma unroll
            for (int nc = 0; nc < 4; nc++) {
                int n = nw*32 + nc*8 + nf;
                float b0 = __ldg(bias + n), b1 = __ldg(bias + n + 1);
                obp[(size_t)n*HWSZ]         = acc[mt*4+nc][0] + b0;
                obp[(size_t)(n+1)*HWSZ]     = acc[mt*4+nc][1] + b1;
                obp[(size_t)n*HWSZ + 8]     = acc[mt*4+nc][2] + b0;
                obp[(size_t)(n+1)*HWSZ + 8] = acc[mt*4+nc][3] + b1;
            }
        }
    }
}

// ---------------------------------------------------------------------------
extern "C" void kernel_launch(void* const* d_in, const int* in_sizes, int n_in,
                              void* d_out, int out_size) {
    const float* x    = (const float*)d_in[0];  // [4,64,128,128]
    const float* wt   = (const float*)d_in[1];  // [64,64,3,3]
    const float* bias = (const float*)d_in[2];  // [64]
    const float* owt  = (const float*)d_in[3];  // [27,64,3,3]
    const float* ob   = (const float*)d_in[4];  // [27]
    float* out = (float*)d_out;                 // [4,64,128,128]

    cudaFuncSetAttribute(fused_dcn_kernel, cudaFuncAttributeMaxDynamicSharedMemorySize, F_TOT);

    x8_kernel<<<2048, 256>>>(x);
    prep_kernel<<<144, 256>>>(wt, owt);
    fused_dcn_kernel<<<1024, 128, F_TOT>>>(ob, bias, out);
}

// round 16
// speedup vs baseline: 1.2937x; 1.2937x over previous
#include <cuda_runtime.h>
#include <cuda_bf16.h>
#include <math.h>
#include <stdint.h>

#define BB 4
#define CIN 64
#define HH 128
#define WW 128
#define HWSZ (HH*WW)
#define COUT 64
#define C27 27
#define CK 576  // CIN*9

// ---------------- device scratch (no allocs allowed) ----------------
// main-conv B per tap: [k][oc 64][c 64] bf16 hi/lo
__device__ __align__(16) __nv_bfloat16 g_wBh[9*4096];
__device__ __align__(16) __nv_bfloat16 g_wBl[9*4096];
// offset-conv B per tap: [k][oc 32 (27 padded)][c 64] bf16 hi/lo
__device__ __align__(16) __nv_bfloat16 g_oBh[9*2048];
__device__ __align__(16) __nv_bfloat16 g_oBl[9*2048];

typedef unsigned long long u64;

// ---------------- helpers ----------------
__device__ __forceinline__ uint32_t smem_u32(const void* p) {
    uint32_t a;
    asm("{ .reg .u64 t; cvta.to.shared.u64 t, %1; cvt.u32.u64 %0, t; }" : "=r"(a) : "l"(p));
    return a;
}
__device__ __forceinline__ void cp_async16(uint32_t smem_dst, const void* gsrc) {
    asm volatile("cp.async.cg.shared.global [%0], [%1], 16;" :: "r"(smem_dst), "l"(gsrc));
}
__device__ __forceinline__ void sts128(uint32_t addr, uint32_t r0, uint32_t r1, uint32_t r2, uint32_t r3) {
    asm volatile("st.shared.v4.b32 [%0], {%1, %2, %3, %4};" :: "r"(addr), "r"(r0), "r"(r1), "r"(r2), "r"(r3) : "memory");
}
__device__ __forceinline__ void ldsm4(uint32_t a, uint32_t& r0, uint32_t& r1, uint32_t& r2, uint32_t& r3) {
    asm volatile("ldmatrix.sync.aligned.m8n8.x4.shared.b16 {%0,%1,%2,%3}, [%4];"
                 : "=r"(r0), "=r"(r1), "=r"(r2), "=r"(r3) : "r"(a));
}
__device__ __forceinline__ void mma16816(float* d, const uint32_t* a, const uint32_t* b) {
    asm volatile("mma.sync.aligned.m16n8k16.row.col.f32.bf16.bf16.f32 "
                 "{%0,%1,%2,%3}, {%4,%5,%6,%7}, {%8,%9}, {%0,%1,%2,%3};"
                 : "+f"(d[0]), "+f"(d[1]), "+f"(d[2]), "+f"(d[3])
                 : "r"(a[0]), "r"(a[1]), "r"(a[2]), "r"(a[3]), "r"(b[0]), "r"(b[1]));
}
// split f32 pair -> bf16x2 hi (truncate) + bf16x2 lo (residual, rounded)
__device__ __forceinline__ void split2(float v0, float v1, uint32_t& hi, uint32_t& lo) {
    uint32_t b0 = __float_as_uint(v0) & 0xFFFF0000u;
    uint32_t b1 = __float_as_uint(v1) & 0xFFFF0000u;
    hi = (b0 >> 16) | b1;
    float l0 = v0 - __uint_as_float(b0);
    float l1 = v1 - __uint_as_float(b1);
    asm("cvt.rn.bf16x2.f32 %0, %1, %2;" : "=r"(lo) : "f"(l1), "f"(l0));
}

#define PITCH 144

// ---------------------------------------------------------------------------
// Kernel 0: weight prep -> bf16 hi/lo B tiles for both convs
// ---------------------------------------------------------------------------
__global__ void prep_kernel(const float* __restrict__ wt, const float* __restrict__ owt) {
    int idx = blockIdx.x * blockDim.x + threadIdx.x;    // 144*256 = 36864
    if (idx < 9*4096) {
        int k  = idx >> 12;
        int oc = (idx >> 6) & 63;
        int c  = idx & 63;
        float w = wt[oc*CK + c*9 + k];
        uint32_t wb  = __float_as_uint(w);
        uint32_t hib = wb & 0xFFFF0000u;
        int d = k*4096 + oc*64 + c;
        ((uint16_t*)g_wBh)[d] = (uint16_t)(hib >> 16);
        g_wBl[d] = __float2bfloat16(w - __uint_as_float(hib));
    }
    if (idx < 9*2048) {
        int k  = idx >> 11;
        int oc = (idx >> 6) & 31;
        int c  = idx & 63;
        float w = (oc < C27) ? owt[oc*CK + c*9 + k] : 0.f;
        uint32_t wb  = __float_as_uint(w);
        uint32_t hib = wb & 0xFFFF0000u;
        int d = k*2048 + oc*64 + c;
        ((uint16_t*)g_oBh)[d] = (uint16_t)(hib >> 16);
        g_oBl[d] = __float2bfloat16(w - __uint_as_float(hib));
    }
}

// ---------------------------------------------------------------------------
// Fused kernel: offset/mask conv (phase 1) + deformable conv (phase 2).
// R16: identical to R14 (NCHW scalar gathers, 2x2 warp tiles, strips,
// tap stagger) except __launch_bounds__(128, 5) -> 5 CTAs/SM (regs <= 102).
// ---------------------------------------------------------------------------
#define FA_HI 0              // 66 rows * 144 = 9504
#define FA_LO 9504
#define FB_HI 19008
#define FB_LO 28224
#define FOM   37440          // om smem: [27][64] f32 = 6912 B
#define F_TOT 44352

__global__ __launch_bounds__(128, 5) void fused_dcn_kernel(const float* __restrict__ x,
                                                           const float* __restrict__ ob,
                                                           const float* __restrict__ bias,
                                                           float* __restrict__ out) {
    extern __shared__ __align__(16) char smem[];
    uint32_t sb = smem_u32(smem);
    int tid  = threadIdx.x;
    int lane = tid & 31, wid = tid >> 5;       // 4 warps, 2x2 tiling
    int mw   = wid & 1;                        // warp M row (m32)
    int nw   = wid >> 1;                       // warp N col
    int b    = blockIdx.x >> 8;                // 256 blocks per image
    int h    = (blockIdx.x >> 1) & 127;
    int px0  = (blockIdx.x & 1) * 64;          // which half-row
    int pxl  = tid & 63;                       // local px 0..63
    int px   = px0 + pxl;                      // w coordinate
    int c0   = (tid >> 6) * 32;                // 2 threads per px
    int kst  = (int)(blockIdx.x % 9u);         // tap stagger (phase 2)
    int kst3 = (int)(blockIdx.x % 3u);         // strip stagger (phase 1)

    const float* xb = x + (size_t)b * CIN * HWSZ;

    int seg = lane >> 3, r8 = lane & 7;
    // A ldsm base for an m16 tile at row base R: aBaseH + R*PITCH (+ ks*32)
    uint32_t aBaseH = sb + FA_HI + (uint32_t)(((seg&1)*8 + r8) * PITCH + (seg>>1)*16);
    uint32_t aBaseL = aBaseH + (FA_LO - FA_HI);
    uint32_t aOff0  = (uint32_t)((mw*32)      * PITCH);
    uint32_t aOff1  = (uint32_t)((mw*32 + 16) * PITCH);
    uint32_t bColB  = (uint32_t)((seg&1)*16);
    uint32_t bRowB  = (uint32_t)(((seg>>1)*8 + r8) * PITCH);

    // =====================================================================
    // Phase 1: offset/mask conv (N=32), strip-based A, result -> smem om
    // warp tile: m32 x n16
    // =====================================================================
    {
        float acco[4][4] = {};   // [mt*2 + nc][4]

        #pragma unroll 1
        for (int js = 0; js < 3; js++) {
            int kh = kst3 + js; if (kh >= 3) kh -= 3;

            // ---- build strip: image row h-1+kh, cols px0-1..px0+64, 64 c ----
            #pragma unroll
            for (int it = 0; it < 2; it++) {
                int idx = tid + it*128;
                if (idx < 132) {
                    int r   = idx % 66;
                    int ch2 = idx / 66;
                    int cc0 = ch2 * 32;
                    int row = h - 1 + kh;
                    int col = px0 - 1 + r;
                    bool valid = (row >= 0) && (row < HH) && (col >= 0) && (col < WW);
                    const float* xs = xb + row*WW + col;
                    #pragma unroll
                    for (int g = 0; g < 4; g++) {
                        int cc = cc0 + g*8;
                        float v[8];
                        #pragma unroll
                        for (int j8 = 0; j8 < 8; j8++)
                            v[j8] = valid ? __ldg(xs + (size_t)(cc+j8) * HWSZ) : 0.f;
                        uint32_t hi[4], lo[4];
                        #pragma unroll
                        for (int j4 = 0; j4 < 4; j4++) split2(v[2*j4], v[2*j4+1], hi[j4], lo[j4]);
                        uint32_t off = (uint32_t)(r*PITCH + cc*2);
                        sts128(sb + FA_HI + off, hi[0], hi[1], hi[2], hi[3]);
                        sts128(sb + FA_LO + off, lo[0], lo[1], lo[2], lo[3]);
                    }
                }
            }

            // ---- 3 kw taps over this strip ----
            #pragma unroll 1
            for (int kw = 0; kw < 3; kw++) {
                int k = kh*3 + kw;

                // stage offset B tiles (hi 4KB + lo 4KB = 512 x 16B chunks)
                #pragma unroll
                for (int i = 0; i < 4; i++) {
                    int e   = tid + i*128;
                    int t8  = e >> 8;
                    int cnk = e & 255;
                    int row = cnk >> 3, c16 = (cnk & 7) * 16;
                    const char* src = (t8 ? (const char*)g_oBl : (const char*)g_oBh)
                                      + (size_t)k*4096 + row*128 + c16;
                    uint32_t dst = sb + (t8 ? FB_LO : FB_HI) + (uint32_t)(row*PITCH + c16);
                    cp_async16(dst, src);
                }
                asm volatile("cp.async.commit_group;");
                asm volatile("cp.async.wait_group 0;");
                __syncthreads();   // B(k) + (first kw: strip) visible

                // MMA: A base shifted by kw rows within the strip
                uint32_t aShift = (uint32_t)(kw * PITCH);
                #pragma unroll
                for (int ks = 0; ks < 4; ks++) {
                    uint32_t ah[2][4], al[2][4];
                    ldsm4(aBaseH + aOff0 + aShift + ks*32, ah[0][0], ah[0][1], ah[0][2], ah[0][3]);
                    ldsm4(aBaseL + aOff0 + aShift + ks*32, al[0][0], al[0][1], al[0][2], al[0][3]);
                    ldsm4(aBaseH + aOff1 + aShift + ks*32, ah[1][0], ah[1][1], ah[1][2], ah[1][3]);
                    ldsm4(aBaseL + aOff1 + aShift + ks*32, al[1][0], al[1][1], al[1][2], al[1][3]);
                    uint32_t bh[2][2], bl[2][2];
                    {
                        uint32_t ra = bRowB + (uint32_t)(nw*16*PITCH) + bColB + ks*32;
                        ldsm4(sb + FB_HI + ra, bh[0][0], bh[0][1], bh[1][0], bh[1][1]);
                        ldsm4(sb + FB_LO + ra, bl[0][0], bl[0][1], bl[1][0], bl[1][1]);
                    }
                    #pragma unroll
                    for (int mt = 0; mt < 2; mt++)
                        #pragma unroll
                        for (int nc = 0; nc < 2; nc++) {
                            mma16816(acco[mt*2+nc], ah[mt], bh[nc]);
                            mma16816(acco[mt*2+nc], ah[mt], bl[nc]);
                            mma16816(acco[mt*2+nc], al[mt], bh[nc]);
                        }
                }
                __syncthreads();   // B / strip safe to overwrite
            }
        }

        // epilogue -> smem om buffer [27][64] f32 (bias + sigmoid on mask rows)
        {
            int nf = (lane & 3) * 2;
            #pragma unroll
            for (int mt = 0; mt < 2; mt++) {
                int ml = mw*32 + mt*16 + (lane >> 2);
                #pragma unroll
                for (int nc = 0; nc < 2; nc++) {
                    #pragma unroll
                    for (int half = 0; half < 2; half++) {
                        int nn = nw*16 + nc*8 + nf + half;
                        if (nn < C27) {
                            float bo = __ldg(ob + nn);
                            float v0 = acco[mt*2+nc][half]     + bo;   // row ml
                            float v1 = acco[mt*2+nc][half + 2] + bo;   // row ml+8
                            if (nn >= 18) {
                                v0 = 1.f / (1.f + __expf(-v0));
                                v1 = 1.f / (1.f + __expf(-v1));
                            }
                            uint32_t oa = sb + FOM + (uint32_t)((nn*64 + ml) * 4);
                            asm volatile("st.shared.f32 [%0], %1;" :: "r"(oa), "f"(v0) : "memory");
                            asm volatile("st.shared.f32 [%0], %1;" :: "r"(oa + 32), "f"(v1) : "memory");
                        }
                    }
                }
            }
        }
        __syncthreads();
    }

    // =====================================================================
    // Phase 2: deformable conv (N=64), om read from smem
    // warp tile: m32 x n32
    // =====================================================================
    float acc[8][4] = {};   // [mt*4 + nc][4]

    #pragma unroll 1
    for (int j = 0; j < 9; j++) {
        int k = kst + j; if (k >= 9) k -= 9;

        // stage main B tiles (hi+lo, 1024 x 16B chunks)
        #pragma unroll
        for (int i = 0; i < 8; i++) {
            int e   = tid + i*128;
            int t8  = e >> 9;
            int cnk = e & 511;
            int row = cnk >> 3, c16 = (cnk & 7) * 16;
            const char* src = (t8 ? (const char*)g_wBl : (const char*)g_wBh)
                              + (size_t)k*8192 + row*128 + c16;
            uint32_t dst = sb + (t8 ? FB_LO : FB_HI) + (uint32_t)(row*PITCH + c16);
            cp_async16(dst, src);
        }
        asm volatile("cp.async.commit_group;");

        // om from smem
        float dy, dx, m;
        {
            uint32_t oa = sb + FOM + (uint32_t)(pxl * 4);
            asm volatile("ld.shared.f32 %0, [%1];" : "=f"(dy) : "r"(oa + (uint32_t)(k*256)));
            asm volatile("ld.shared.f32 %0, [%1];" : "=f"(dx) : "r"(oa + (uint32_t)((9+k)*256)));
            asm volatile("ld.shared.f32 %0, [%1];" : "=f"(m)  : "r"(oa + (uint32_t)((18+k)*256)));
        }

        // bilinear params
        int kh = k / 3, kw = k - kh*3;
        float hh = (float)(h - 1 + kh) + dy;
        float ww = (float)(px - 1 + kw) + dx;
        float h0f = floorf(hh), w0f = floorf(ww);
        float lh = hh - h0f, lw = ww - w0f;
        int h0 = (int)h0f, w0 = (int)w0f, h1 = h0+1, w1 = w0+1;
        bool vh0 = (h0>=0)&&(h0<HH), vh1 = (h1>=0)&&(h1<HH);
        bool vw0 = (w0>=0)&&(w0<WW), vw1 = (w1>=0)&&(w1<WW);
        int ch0 = min(max(h0,0),HH-1), ch1 = min(max(h1,0),HH-1);
        int cw0 = min(max(w0,0),WW-1), cw1 = min(max(w1,0),WW-1);
        int i00 = ch0*WW+cw0, i01 = ch0*WW+cw1;
        int i10 = ch1*WW+cw0, i11 = ch1*WW+cw1;
        float w00 = (1.f-lh)*(1.f-lw)*m*((vh0&&vw0)?1.f:0.f);
        float w01 = (1.f-lh)*lw      *m*((vh0&&vw1)?1.f:0.f);
        float w10 = lh*(1.f-lw)      *m*((vh1&&vw0)?1.f:0.f);
        float w11 = lh*lw            *m*((vh1&&vw1)?1.f:0.f);

        // produce A tile: front-batched corner loads (32 in flight)
        #pragma unroll 1
        for (int g = 0; g < 4; g++) {
            int cc = c0 + g*8;
            const float* xc = xb + (size_t)cc * HWSZ;
            float va[8], vb[8], vc[8], vd[8];
            #pragma unroll
            for (int j8 = 0; j8 < 8; j8++) va[j8] = __ldg(xc + (size_t)j8*HWSZ + i00);
            #pragma unroll
            for (int j8 = 0; j8 < 8; j8++) vb[j8] = __ldg(xc + (size_t)j8*HWSZ + i01);
            #pragma unroll
            for (int j8 = 0; j8 < 8; j8++) vc[j8] = __ldg(xc + (size_t)j8*HWSZ + i10);
            #pragma unroll
            for (int j8 = 0; j8 < 8; j8++) vd[j8] = __ldg(xc + (size_t)j8*HWSZ + i11);
            float v[8];
            #pragma unroll
            for (int j8 = 0; j8 < 8; j8++) {
                float t = w00 * va[j8];
                t = fmaf(w01, vb[j8], t);
                t = fmaf(w10, vc[j8], t);
                t = fmaf(w11, vd[j8], t);
                v[j8] = t;
            }
            uint32_t hi[4], lo[4];
            #pragma unroll
            for (int j4 = 0; j4 < 4; j4++) split2(v[2*j4], v[2*j4+1], hi[j4], lo[j4]);
            uint32_t off = (uint32_t)(pxl*PITCH + cc*2);
            sts128(sb + FA_HI + off, hi[0], hi[1], hi[2], hi[3]);
            sts128(sb + FA_LO + off, lo[0], lo[1], lo[2], lo[3]);
        }

        asm volatile("cp.async.wait_group 0;");
        __syncthreads();

        // MMA: 4 ks x (4 A-ldsm + 4 B-ldsm + 24 mma), warp tile m32 x n32
        #pragma unroll
        for (int ks = 0; ks < 4; ks++) {
            uint32_t ah[2][4], al[2][4];
            ldsm4(aBaseH + aOff0 + ks*32, ah[0][0], ah[0][1], ah[0][2], ah[0][3]);
            ldsm4(aBaseL + aOff0 + ks*32, al[0][0], al[0][1], al[0][2], al[0][3]);
            ldsm4(aBaseH + aOff1 + ks*32, ah[1][0], ah[1][1], ah[1][2], ah[1][3]);
            ldsm4(aBaseL + aOff1 + ks*32, al[1][0], al[1][1], al[1][2], al[1][3]);
            uint32_t bh[4][2], bl[4][2];
            #pragma unroll
            for (int q = 0; q < 2; q++) {
                uint32_t ra = bRowB + (uint32_t)((nw*32 + q*16)*PITCH) + bColB + ks*32;
                ldsm4(sb + FB_HI + ra, bh[2*q][0], bh[2*q][1], bh[2*q+1][0], bh[2*q+1][1]);
                ldsm4(sb + FB_LO + ra, bl[2*q][0], bl[2*q][1], bl[2*q+1][0], bl[2*q+1][1]);
            }
            #pragma unroll
            for (int mt = 0; mt < 2; mt++)
                #pragma unroll
                for (int nc = 0; nc < 4; nc++) {
                    mma16816(acc[mt*4+nc], ah[mt], bh[nc]);
                    mma16816(acc[mt*4+nc], ah[mt], bl[nc]);
                    mma16816(acc[mt*4+nc], al[mt], bh[nc]);
                }
        }
        __syncthreads();
    }

    // ---- epilogue ----
    {
        int nf = (lane & 3) * 2;
        #pragma unroll
        for (int mt = 0; mt < 2; mt++) {
            int ml = mw*32 + mt*16 + (lane >> 2);
            float* obp = out + (size_t)b * COUT * HWSZ + (h << 7) + px0 + ml;
            #pragma unroll
            for (int nc = 0; nc < 4; nc++) {
                int n = nw*32 + nc*8 + nf;
                float b0 = __ldg(bias + n), b1 = __ldg(bias + n + 1);
                obp[(size_t)n*HWSZ]         = acc[mt*4+nc][0] + b0;
                obp[(size_t)(n+1)*HWSZ]     = acc[mt*4+nc][1] + b1;
                obp[(size_t)n*HWSZ + 8]     = acc[mt*4+nc][2] + b0;
                obp[(size_t)(n+1)*HWSZ + 8] = acc[mt*4+nc][3] + b1;
            }
        }
    }
}

// ---------------------------------------------------------------------------
extern "C" void kernel_launch(void* const* d_in, const int* in_sizes, int n_in,
                              void* d_out, int out_size) {
    const float* x    = (const float*)d_in[0];  // [4,64,128,128]
    const float* wt   = (const float*)d_in[1];  // [64,64,3,3]
    const float* bias = (const float*)d_in[2];  // [64]
    const float* owt  = (const float*)d_in[3];  // [27,64,3,3]
    const float* ob   = (const float*)d_in[4];  // [27]
    float* out = (float*)d_out;                 // [4,64,128,128]

    cudaFuncSetAttribute(fused_dcn_kernel, cudaFuncAttributeMaxDynamicSharedMemorySize, F_TOT);

    prep_kernel<<<144, 256>>>(wt, owt);
    fused_dcn_kernel<<<1024, 128, F_TOT>>>(x, ob, bias, out);
}